// round 1
// baseline (speedup 1.0000x reference)
#include <cuda_runtime.h>
#include <math.h>
#include <stdint.h>

// ---------------- problem constants ----------------
#define T_    4
#define B_    32
#define N_    196
#define C_    384
#define H_    8
#define D_    48
#define HID_  1536
#define TB_   128           // T*B
#define NC_   75264         // N*C
#define BNC_  2408448       // B*N*C
#define TBN_  25088         // T*B*N
#define BN_   6272          // B*N
#define MH_   9633792       // BN_*HID_ == TBN_*C_  (identical!)

// ---------------- scratch (device globals; no runtime alloc allowed) ----------------
__device__ float g_bq[MH_];
__device__ float g_bk[MH_];
__device__ float g_bv[MH_];
__device__ float g_ab[MH_];
__device__ float g_af[MH_];
__device__ float g_curr[4 * MH_];
__device__ float g_syn[MH_];
__device__ float g_mem[MH_];
__device__ float g_spk[4 * MH_];
__device__ float g_R[MH_];
__device__ float g_l[MH_];
__device__ float g_ga[MH_];
__device__ float g_gl[MH_];
__device__ float g_fu[MH_];
__device__ float g_o[MH_];
__device__ float g_part[98 * 768];
__device__ float g_stats[768];   // [0:384) mu, [384:768) rstd

// ---------------- GEMM: C[M,N] = A[M,K] @ W[N,K]^T + bias[N]  (all dims %64==0, K%16==0) --------
#define GBM 64
#define GBN 64
#define GBK 16

__global__ __launch_bounds__(256)
void gemm_nt(const float* __restrict__ A, const float* __restrict__ W,
             const float* __restrict__ bias, float* __restrict__ C,
             int M, int N, int K) {
    __shared__ float As[GBK][GBM + 1];
    __shared__ float Ws[GBK][GBN + 1];
    const int tid = threadIdx.x;
    const int bm = blockIdx.y * GBM;
    const int bn = blockIdx.x * GBN;
    const int tx = tid & 15;
    const int ty = tid >> 4;

    float acc[4][4] = {};

    for (int k0 = 0; k0 < K; k0 += GBK) {
#pragma unroll
        for (int i = 0; i < 4; i++) {
            int idx = tid + i * 256;
            int m = idx >> 4;
            int kk = idx & 15;
            As[kk][m] = A[(size_t)(bm + m) * K + k0 + kk];
            Ws[kk][m] = W[(size_t)(bn + m) * K + k0 + kk];
        }
        __syncthreads();
#pragma unroll
        for (int kk = 0; kk < GBK; kk++) {
            float a[4], b[4];
#pragma unroll
            for (int i = 0; i < 4; i++) a[i] = As[kk][ty * 4 + i];
#pragma unroll
            for (int j = 0; j < 4; j++) b[j] = Ws[kk][tx * 4 + j];
#pragma unroll
            for (int i = 0; i < 4; i++)
#pragma unroll
                for (int j = 0; j < 4; j++)
                    acc[i][j] += a[i] * b[j];
        }
        __syncthreads();
    }
#pragma unroll
    for (int i = 0; i < 4; i++) {
        int row = bm + ty * 4 + i;
#pragma unroll
        for (int j = 0; j < 4; j++) {
            int col = bn + tx * 4 + j;
            C[(size_t)row * N + col] = acc[i][j] + bias[col];
        }
    }
}

// ---------------- LIF scan (in-place): buf[t*stride + idx], t = 0..steps-1 ----------------
__global__ void lif_seq(float* __restrict__ buf, int steps, long stride, long nelem,
                        const float* __restrict__ lif_w, int widx) {
    long idx = (long)blockIdx.x * blockDim.x + threadIdx.x;
    if (idx >= nelem) return;
    float decay = 1.0f / (1.0f + expf(-lif_w[widx]));
    float v = 0.0f;
    for (int t = 0; t < steps; t++) {
        long o = (long)t * stride + idx;
        float x = buf[o];
        v = v + (x - v) * decay;
        float s = (v >= 1.0f) ? 1.0f : 0.0f;
        buf[o] = s;
        v *= (1.0f - s);
    }
}

// ---------------- spiking attention, one block per (t*B+b, h) ----------------
__global__ __launch_bounds__(256)
void attn_kernel(const float* __restrict__ sq, const float* __restrict__ sk,
                 const float* __restrict__ sv, float* __restrict__ abuf) {
    const int tb = blockIdx.x >> 3;
    const int h = blockIdx.x & 7;
    __shared__ unsigned long long qb[N_], kb[N_], vb[N_];
    __shared__ unsigned char cnt[N_ * 200];
    const int tid = threadIdx.x;

    for (int i = tid; i < N_; i += 256) { qb[i] = 0ull; kb[i] = 0ull; vb[i] = 0ull; }
    __syncthreads();

    const long base = (long)tb * NC_ + h * D_;
    for (int e = tid; e < N_ * D_; e += 256) {
        int n = e / D_, d = e % D_;
        long off = base + (long)n * C_ + d;
        unsigned long long bit = 1ull << d;
        if (sq[off] != 0.0f) atomicOr(&qb[n], bit);
        if (sk[off] != 0.0f) atomicOr(&kb[n], bit);
        if (sv[off] != 0.0f) atomicOr(&vb[n], bit);
    }
    __syncthreads();

    for (int i = tid; i < N_ * N_; i += 256) {
        int n = i / N_, m = i - n * N_;
        cnt[n * 200 + m] = (unsigned char)__popcll(qb[n] & kb[m]);
    }
    __syncthreads();

    const float scale = 0.14433756729740643f;  // 48^-0.5
    for (int o = tid; o < N_ * D_; o += 256) {
        int n = o / D_, d = o - n * D_;
        const unsigned char* crow = &cnt[n * 200];
        int acc = 0;
#pragma unroll 4
        for (int m = 0; m < N_; m++)
            acc += (int)crow[m] * (int)((vb[m] >> d) & 1ull);
        // faithful swapaxes(3,4).reshape: write to flat index h*D*N + d*N + n
        abuf[(long)tb * NC_ + h * (D_ * N_) + d * N_ + n] = scale * (float)acc;
    }
}

// ---------------- LSM (RSynaptic) elementwise steps ----------------
__global__ void lsm_step0(const float* __restrict__ curr, const float* __restrict__ rec_b,
                          float* __restrict__ syn, float* __restrict__ mem,
                          float* __restrict__ spk) {
    long idx = (long)blockIdx.x * blockDim.x + threadIdx.x;
    if (idx >= (long)MH_) return;
    int hc = (int)(idx % HID_);
    float s = curr[idx] + rec_b[hc];
    float m = s;               // 0.8*0 + syn - 0
    syn[idx] = s;
    mem[idx] = m;
    spk[idx] = (m - 1.0f >= 0.0f) ? 1.0f : 0.0f;
}

__global__ void lsm_step(const float* __restrict__ curr_t, const float* __restrict__ R,
                         float* __restrict__ syn, float* __restrict__ mem,
                         const float* __restrict__ spk_prev, float* __restrict__ spk_out) {
    long idx = (long)blockIdx.x * blockDim.x + threadIdx.x;
    if (idx >= (long)MH_) return;
    float sp = spk_prev[idx];
    float s = 0.9f * syn[idx] + curr_t[idx] + R[idx];   // R already includes rec_b
    float m = 0.8f * mem[idx] + s - sp * 1.0f;
    syn[idx] = s;
    mem[idx] = m;
    spk_out[idx] = (m - 1.0f >= 0.0f) ? 1.0f : 0.0f;
}

// ---------------- BatchNorm stats (deterministic 2-stage) ----------------
__global__ void bn_partial(const float* __restrict__ X, float* __restrict__ part) {
    int c = threadIdx.x;               // 384 threads
    long r0 = (long)blockIdx.x * 256;  // 98 blocks * 256 rows = 25088
    float s = 0.0f, s2 = 0.0f;
    for (int r = 0; r < 256; r++) {
        float v = X[(r0 + r) * C_ + c];
        s += v;
        s2 += v * v;
    }
    part[blockIdx.x * 768 + c] = s;
    part[blockIdx.x * 768 + 384 + c] = s2;
}

__global__ void bn_finalize(const float* __restrict__ part, float* __restrict__ stats) {
    int c = threadIdx.x;  // 384
    float s = 0.0f, s2 = 0.0f;
    for (int p = 0; p < 98; p++) {
        s += part[p * 768 + c];
        s2 += part[p * 768 + 384 + c];
    }
    const float inv = 1.0f / 25088.0f;
    float m = s * inv;
    float var = s2 * inv - m * m;
    stats[c] = m;
    stats[384 + c] = 1.0f / sqrtf(var + 1e-5f);
}

// ---------------- fused BN-apply + 4-step LIF (+ optional residual into d_out) -------
__global__ void bn_lif4(const float* __restrict__ lin, float* __restrict__ out,
                        const float* __restrict__ stats,
                        const float* __restrict__ gamma, const float* __restrict__ beta,
                        const float* __restrict__ lif_w, int widx,
                        const float* __restrict__ xadd) {
    long idx = (long)blockIdx.x * blockDim.x + threadIdx.x;
    if (idx >= (long)BNC_) return;
    int c = (int)(idx % C_);
    float mu = stats[c], rstd = stats[384 + c];
    float gg = gamma[c], bb = beta[c];
    float decay = 1.0f / (1.0f + expf(-lif_w[widx]));
    float v = 0.0f;
    for (int t = 0; t < 4; t++) {
        long o = (long)t * BNC_ + idx;
        float xv = (lin[o] - mu) * rstd * gg + bb;
        v = v + (xv - v) * decay;
        float s = (v >= 1.0f) ? 1.0f : 0.0f;
        v *= (1.0f - s);
        if (xadd) out[o] = xadd[o] + s;
        else      out[o] = s;
    }
}

// ---------------- ARIG fusion elementwise ----------------
__global__ void fuse_kernel(const float* __restrict__ af, const float* __restrict__ lf,
                            const float* __restrict__ ga, const float* __restrict__ gl,
                            float* __restrict__ fu) {
    long idx = (long)blockIdx.x * blockDim.x + threadIdx.x;
    if (idx >= (long)MH_) return;
    float gate_attn = 1.0f / (1.0f + expf(-gl[idx]));  // sigmoid(wlsm(lf))
    float gate_lsm  = 1.0f / (1.0f + expf(-ga[idx]));  // sigmoid(watt(af))
    fu[idx] = af[idx] * gate_attn + lf[idx] * gate_lsm;
}

// ---------------- launch ----------------
extern "C" void kernel_launch(void* const* d_in, const int* in_sizes, int n_in,
                              void* d_out, int out_size) {
    const float* x      = (const float*)d_in[0];
    const float* q_w    = (const float*)d_in[1];
    const float* q_b    = (const float*)d_in[2];
    const float* k_w    = (const float*)d_in[3];
    const float* k_b    = (const float*)d_in[4];
    const float* v_w    = (const float*)d_in[5];
    const float* v_b    = (const float*)d_in[6];
    const float* ap_w   = (const float*)d_in[7];
    const float* ap_b   = (const float*)d_in[8];
    const float* fc1_w  = (const float*)d_in[9];
    const float* fc1_b  = (const float*)d_in[10];
    const float* rec_w  = (const float*)d_in[11];
    const float* rec_b  = (const float*)d_in[12];
    const float* fc2_w  = (const float*)d_in[13];
    const float* fc2_b  = (const float*)d_in[14];
    const float* bnl_g  = (const float*)d_in[15];
    const float* bnl_b  = (const float*)d_in[16];
    const float* watt_w = (const float*)d_in[17];
    const float* watt_b = (const float*)d_in[18];
    const float* wlsm_w = (const float*)d_in[19];
    const float* wlsm_b = (const float*)d_in[20];
    const float* fp_w   = (const float*)d_in[21];
    const float* fp_b   = (const float*)d_in[22];
    const float* bnf_g  = (const float*)d_in[23];
    const float* bnf_b  = (const float*)d_in[24];
    const float* lif_w  = (const float*)d_in[25];
    float* out = (float*)d_out;

    float *bq, *bk, *bv, *ab, *af, *curr, *syn, *mem, *spk, *R, *l, *ga, *gl, *fu, *o, *part, *stats;
    cudaGetSymbolAddress((void**)&bq, g_bq);
    cudaGetSymbolAddress((void**)&bk, g_bk);
    cudaGetSymbolAddress((void**)&bv, g_bv);
    cudaGetSymbolAddress((void**)&ab, g_ab);
    cudaGetSymbolAddress((void**)&af, g_af);
    cudaGetSymbolAddress((void**)&curr, g_curr);
    cudaGetSymbolAddress((void**)&syn, g_syn);
    cudaGetSymbolAddress((void**)&mem, g_mem);
    cudaGetSymbolAddress((void**)&spk, g_spk);
    cudaGetSymbolAddress((void**)&R, g_R);
    cudaGetSymbolAddress((void**)&l, g_l);
    cudaGetSymbolAddress((void**)&ga, g_ga);
    cudaGetSymbolAddress((void**)&gl, g_gl);
    cudaGetSymbolAddress((void**)&fu, g_fu);
    cudaGetSymbolAddress((void**)&o, g_o);
    cudaGetSymbolAddress((void**)&part, g_part);
    cudaGetSymbolAddress((void**)&stats, g_stats);

    const dim3 gC(C_ / 64, TBN_ / 64);    // (6, 392)  M=25088, N=384
    const dim3 gH(HID_ / 64, TBN_ / 64);  // (24, 392) fc1
    const dim3 gR(HID_ / 64, BN_ / 64);   // (24, 98)  rec
    const int nb75k = (NC_ + 255) / 256;      // 294
    const int nbBNC = (BNC_ + 255) / 256;     // 9408
    const int nbMH  = (MH_ + 255) / 256;      // 37632

    // --- SSA branch: q/k/v linears then 128-step LIF scans (in place) ---
    gemm_nt<<<gC, 256>>>(x, q_w, q_b, bq, TBN_, C_, C_);
    gemm_nt<<<gC, 256>>>(x, k_w, k_b, bk, TBN_, C_, C_);
    gemm_nt<<<gC, 256>>>(x, v_w, v_b, bv, TBN_, C_, C_);
    lif_seq<<<nb75k, 256>>>(bq, TB_, NC_, NC_, lif_w, 0);
    lif_seq<<<nb75k, 256>>>(bk, TB_, NC_, NC_, lif_w, 1);
    lif_seq<<<nb75k, 256>>>(bv, TB_, NC_, NC_, lif_w, 2);

    attn_kernel<<<TB_ * H_, 256>>>(bq, bk, bv, ab);
    lif_seq<<<nbBNC, 256>>>(ab, T_, BNC_, BNC_, lif_w, 3);          // 4-step LIF over T

    gemm_nt<<<gC, 256>>>(ab, ap_w, ap_b, af, TBN_, C_, C_);
    lif_seq<<<nb75k, 256>>>(af, TB_, NC_, NC_, lif_w, 4);           // af = spikes

    // --- LSM branch ---
    gemm_nt<<<gH, 256>>>(x, fc1_w, fc1_b, curr, TBN_, HID_, C_);
    lsm_step0<<<nbMH, 256>>>(curr, rec_b, syn, mem, spk);
    for (int t = 1; t < T_; t++) {
        gemm_nt<<<gR, 256>>>(spk + (size_t)(t - 1) * MH_, rec_w, rec_b, R, BN_, HID_, HID_);
        lsm_step<<<nbMH, 256>>>(curr + (size_t)t * MH_, R, syn, mem,
                                spk + (size_t)(t - 1) * MH_, spk + (size_t)t * MH_);
    }
    gemm_nt<<<gC, 256>>>(spk, fc2_w, fc2_b, l, TBN_, C_, HID_);
    bn_partial<<<98, 384>>>(l, part);
    bn_finalize<<<1, 384>>>(part, stats);
    bn_lif4<<<nbBNC, 256>>>(l, l, stats, bnl_g, bnl_b, lif_w, 5, nullptr);  // lf = spikes (in place)

    // --- ARIG fusion ---
    gemm_nt<<<gC, 256>>>(af, watt_w, watt_b, ga, TBN_, C_, C_);
    gemm_nt<<<gC, 256>>>(l,  wlsm_w, wlsm_b, gl, TBN_, C_, C_);
    fuse_kernel<<<nbMH, 256>>>(af, l, ga, gl, fu);
    gemm_nt<<<gC, 256>>>(fu, fp_w, fp_b, o, TBN_, C_, C_);
    bn_partial<<<98, 384>>>(o, part);
    bn_finalize<<<1, 384>>>(part, stats);
    bn_lif4<<<nbBNC, 256>>>(o, out, stats, bnf_g, bnf_b, lif_w, 6, x);  // out = x + spikes
}

// round 2
// speedup vs baseline: 2.0181x; 2.0181x over previous
#include <cuda_runtime.h>
#include <math.h>
#include <stdint.h>

// ---------------- problem constants ----------------
#define T_    4
#define B_    32
#define N_    196
#define C_    384
#define H_    8
#define D_    48
#define HID_  1536
#define TB_   128           // T*B
#define NC_   75264         // N*C
#define BNC_  2408448       // B*N*C
#define TBN_  25088         // T*B*N
#define BN_   6272          // B*N
#define MH_   9633792       // BN_*HID_ == TBN_*C_  (identical!)

// ---------------- scratch (device globals; no runtime alloc allowed) ----------------
__device__ float g_bq[MH_];
__device__ float g_bk[MH_];
__device__ float g_bv[MH_];
__device__ float g_ab[MH_];
__device__ float g_af[MH_];
__device__ float g_curr[4 * MH_];
__device__ float g_syn[MH_];
__device__ float g_mem[MH_];
__device__ float g_spk[4 * MH_];
__device__ float g_R[MH_];
__device__ float g_l[MH_];
__device__ float g_ga[MH_];
__device__ float g_gl[MH_];
__device__ float g_fu[MH_];
__device__ float g_o[MH_];
__device__ float g_part[98 * 768];
__device__ float g_stats[768];   // [0:384) mu, [384:768) rstd

// ================= SGEMM: C[M,N] = A[M,K] @ W[N,K]^T + bias[N] =================
// 128x128 tile, BK=8, 256 threads, 8x8 acc/thread, double-buffered smem.
// Requires M%128==0, N%128==0, K%8==0 (all shapes here satisfy this).
#define BM 128
#define BN 128
#define BK 8

__global__ __launch_bounds__(256, 2)
void sgemm_nt(const float* __restrict__ A, const float* __restrict__ W,
              const float* __restrict__ bias, float* __restrict__ C,
              int M, int N, int K) {
    __shared__ float As[2][BK][BM];
    __shared__ float Bs[2][BK][BN];

    const int tid = threadIdx.x;
    const int bm = blockIdx.y * BM;
    const int bn = blockIdx.x * BN;

    // global load mapping: each thread loads one float4 of A and one of W per k-tile
    const int lr = tid >> 1;            // 0..127 (row within tile)
    const int lc = (tid & 1) * 4;       // 0 or 4 (k offset)
    const float* Ap = A + (size_t)(bm + lr) * K + lc;
    const float* Wp = W + (size_t)(bn + lr) * K + lc;

    // compute mapping
    const int tx = tid & 15;            // 0..15
    const int ty = tid >> 4;            // 0..15

    float acc[8][8] = {};

    // prologue: load k-tile 0 into buffer 0
    float4 av = *(const float4*)Ap;
    float4 wv = *(const float4*)Wp;
    As[0][lc + 0][lr] = av.x; As[0][lc + 1][lr] = av.y;
    As[0][lc + 2][lr] = av.z; As[0][lc + 3][lr] = av.w;
    Bs[0][lc + 0][lr] = wv.x; Bs[0][lc + 1][lr] = wv.y;
    Bs[0][lc + 2][lr] = wv.z; Bs[0][lc + 3][lr] = wv.w;
    __syncthreads();

    const int nk = K / BK;
    for (int kt = 0; kt < nk; kt++) {
        const int cur = kt & 1;
        if (kt + 1 < nk) {
            av = *(const float4*)(Ap + (size_t)(kt + 1) * BK);
            wv = *(const float4*)(Wp + (size_t)(kt + 1) * BK);
        }
#pragma unroll
        for (int kk = 0; kk < BK; kk++) {
            float4 a0 = *(const float4*)&As[cur][kk][ty * 4];
            float4 a1 = *(const float4*)&As[cur][kk][ty * 4 + 64];
            float4 b0 = *(const float4*)&Bs[cur][kk][tx * 4];
            float4 b1 = *(const float4*)&Bs[cur][kk][tx * 4 + 64];
            float a[8] = {a0.x, a0.y, a0.z, a0.w, a1.x, a1.y, a1.z, a1.w};
            float b[8] = {b0.x, b0.y, b0.z, b0.w, b1.x, b1.y, b1.z, b1.w};
#pragma unroll
            for (int i = 0; i < 8; i++)
#pragma unroll
                for (int j = 0; j < 8; j++)
                    acc[i][j] += a[i] * b[j];
        }
        if (kt + 1 < nk) {
            const int nxt = cur ^ 1;
            As[nxt][lc + 0][lr] = av.x; As[nxt][lc + 1][lr] = av.y;
            As[nxt][lc + 2][lr] = av.z; As[nxt][lc + 3][lr] = av.w;
            Bs[nxt][lc + 0][lr] = wv.x; Bs[nxt][lc + 1][lr] = wv.y;
            Bs[nxt][lc + 2][lr] = wv.z; Bs[nxt][lc + 3][lr] = wv.w;
            __syncthreads();
        }
    }

    // epilogue: vectorized stores with bias
#pragma unroll
    for (int i = 0; i < 8; i++) {
        const int row = bm + ty * 4 + (i & 3) + ((i >> 2) << 6);
#pragma unroll
        for (int jb = 0; jb < 2; jb++) {
            const int col = bn + tx * 4 + jb * 64;
            float4 bv4 = *(const float4*)&bias[col];
            float4 v;
            v.x = acc[i][jb * 4 + 0] + bv4.x;
            v.y = acc[i][jb * 4 + 1] + bv4.y;
            v.z = acc[i][jb * 4 + 2] + bv4.z;
            v.w = acc[i][jb * 4 + 3] + bv4.w;
            *(float4*)&C[(size_t)row * N + col] = v;
        }
    }
}

// ---------------- LIF scan (in-place), depth-4 prefetch pipeline ----------------
__global__ void lif_seq(float* __restrict__ buf, int steps, long stride, long nelem,
                        const float* __restrict__ lif_w, int widx) {
    long idx = (long)blockIdx.x * blockDim.x + threadIdx.x;
    if (idx >= nelem) return;
    const float decay = 1.0f / (1.0f + expf(-lif_w[widx]));
    float v = 0.0f;
    float xs[4];
#pragma unroll
    for (int t = 0; t < 4; t++)
        if (t < steps) xs[t] = buf[(long)t * stride + idx];
    for (int t = 0; t < steps; t++) {
        float x = xs[t & 3];
        if (t + 4 < steps) xs[t & 3] = buf[(long)(t + 4) * stride + idx];
        v = v + (x - v) * decay;
        float s = (v >= 1.0f) ? 1.0f : 0.0f;
        buf[(long)t * stride + idx] = s;
        v *= (1.0f - s);
    }
}

// ---------------- spiking attention, one block per (t*B+b, h) ----------------
__global__ __launch_bounds__(256)
void attn_kernel(const float* __restrict__ sq, const float* __restrict__ sk,
                 const float* __restrict__ sv, float* __restrict__ abuf) {
    const int tb = blockIdx.x >> 3;
    const int h = blockIdx.x & 7;
    __shared__ unsigned long long qb[N_], kb[N_], vb[N_];
    __shared__ unsigned char cnt[N_ * 200];
    const int tid = threadIdx.x;

    for (int i = tid; i < N_; i += 256) { qb[i] = 0ull; kb[i] = 0ull; vb[i] = 0ull; }
    __syncthreads();

    const long base = (long)tb * NC_ + h * D_;
    for (int e = tid; e < N_ * D_; e += 256) {
        int n = e / D_, d = e % D_;
        long off = base + (long)n * C_ + d;
        unsigned long long bit = 1ull << d;
        if (sq[off] != 0.0f) atomicOr(&qb[n], bit);
        if (sk[off] != 0.0f) atomicOr(&kb[n], bit);
        if (sv[off] != 0.0f) atomicOr(&vb[n], bit);
    }
    __syncthreads();

    for (int i = tid; i < N_ * N_; i += 256) {
        int n = i / N_, m = i - n * N_;
        cnt[n * 200 + m] = (unsigned char)__popcll(qb[n] & kb[m]);
    }
    __syncthreads();

    const float scale = 0.14433756729740643f;  // 48^-0.5
    for (int o = tid; o < N_ * D_; o += 256) {
        int n = o / D_, d = o - n * D_;
        const unsigned char* crow = &cnt[n * 200];
        int acc = 0;
#pragma unroll 4
        for (int m = 0; m < N_; m++)
            acc += (int)crow[m] * (int)((vb[m] >> d) & 1ull);
        abuf[(long)tb * NC_ + h * (D_ * N_) + d * N_ + n] = scale * (float)acc;
    }
}

// ---------------- LSM (RSynaptic) elementwise steps ----------------
__global__ void lsm_step0(const float* __restrict__ curr, const float* __restrict__ rec_b,
                          float* __restrict__ syn, float* __restrict__ mem,
                          float* __restrict__ spk) {
    long idx = (long)blockIdx.x * blockDim.x + threadIdx.x;
    if (idx >= (long)MH_) return;
    int hc = (int)(idx % HID_);
    float s = curr[idx] + rec_b[hc];
    float m = s;
    syn[idx] = s;
    mem[idx] = m;
    spk[idx] = (m - 1.0f >= 0.0f) ? 1.0f : 0.0f;
}

__global__ void lsm_step(const float* __restrict__ curr_t, const float* __restrict__ R,
                         float* __restrict__ syn, float* __restrict__ mem,
                         const float* __restrict__ spk_prev, float* __restrict__ spk_out) {
    long idx = (long)blockIdx.x * blockDim.x + threadIdx.x;
    if (idx >= (long)MH_) return;
    float sp = spk_prev[idx];
    float s = 0.9f * syn[idx] + curr_t[idx] + R[idx];
    float m = 0.8f * mem[idx] + s - sp * 1.0f;
    syn[idx] = s;
    mem[idx] = m;
    spk_out[idx] = (m - 1.0f >= 0.0f) ? 1.0f : 0.0f;
}

// ---------------- BatchNorm stats (deterministic 2-stage) ----------------
__global__ void bn_partial(const float* __restrict__ X, float* __restrict__ part) {
    int c = threadIdx.x;
    long r0 = (long)blockIdx.x * 256;
    float s = 0.0f, s2 = 0.0f;
    for (int r = 0; r < 256; r++) {
        float v = X[(r0 + r) * C_ + c];
        s += v;
        s2 += v * v;
    }
    part[blockIdx.x * 768 + c] = s;
    part[blockIdx.x * 768 + 384 + c] = s2;
}

__global__ void bn_finalize(const float* __restrict__ part, float* __restrict__ stats) {
    int c = threadIdx.x;
    float s = 0.0f, s2 = 0.0f;
    for (int p = 0; p < 98; p++) {
        s += part[p * 768 + c];
        s2 += part[p * 768 + 384 + c];
    }
    const float inv = 1.0f / 25088.0f;
    float m = s * inv;
    float var = s2 * inv - m * m;
    stats[c] = m;
    stats[384 + c] = 1.0f / sqrtf(var + 1e-5f);
}

// ---------------- fused BN-apply + 4-step LIF (+ optional residual into d_out) -------
__global__ void bn_lif4(const float* __restrict__ lin, float* __restrict__ out,
                        const float* __restrict__ stats,
                        const float* __restrict__ gamma, const float* __restrict__ beta,
                        const float* __restrict__ lif_w, int widx,
                        const float* __restrict__ xadd) {
    long idx = (long)blockIdx.x * blockDim.x + threadIdx.x;
    if (idx >= (long)BNC_) return;
    int c = (int)(idx % C_);
    float mu = stats[c], rstd = stats[384 + c];
    float gg = gamma[c], bb = beta[c];
    float decay = 1.0f / (1.0f + expf(-lif_w[widx]));
    float v = 0.0f;
    float xs[4];
#pragma unroll
    for (int t = 0; t < 4; t++) xs[t] = lin[(long)t * BNC_ + idx];
#pragma unroll
    for (int t = 0; t < 4; t++) {
        long o = (long)t * BNC_ + idx;
        float xv = (xs[t] - mu) * rstd * gg + bb;
        v = v + (xv - v) * decay;
        float s = (v >= 1.0f) ? 1.0f : 0.0f;
        v *= (1.0f - s);
        if (xadd) out[o] = xadd[o] + s;
        else      out[o] = s;
    }
}

// ---------------- ARIG fusion elementwise ----------------
__global__ void fuse_kernel(const float* __restrict__ af, const float* __restrict__ lf,
                            const float* __restrict__ ga, const float* __restrict__ gl,
                            float* __restrict__ fu) {
    long idx = (long)blockIdx.x * blockDim.x + threadIdx.x;
    if (idx >= (long)MH_) return;
    float gate_attn = 1.0f / (1.0f + expf(-gl[idx]));
    float gate_lsm  = 1.0f / (1.0f + expf(-ga[idx]));
    fu[idx] = af[idx] * gate_attn + lf[idx] * gate_lsm;
}

// ---------------- launch ----------------
extern "C" void kernel_launch(void* const* d_in, const int* in_sizes, int n_in,
                              void* d_out, int out_size) {
    const float* x      = (const float*)d_in[0];
    const float* q_w    = (const float*)d_in[1];
    const float* q_b    = (const float*)d_in[2];
    const float* k_w    = (const float*)d_in[3];
    const float* k_b    = (const float*)d_in[4];
    const float* v_w    = (const float*)d_in[5];
    const float* v_b    = (const float*)d_in[6];
    const float* ap_w   = (const float*)d_in[7];
    const float* ap_b   = (const float*)d_in[8];
    const float* fc1_w  = (const float*)d_in[9];
    const float* fc1_b  = (const float*)d_in[10];
    const float* rec_w  = (const float*)d_in[11];
    const float* rec_b  = (const float*)d_in[12];
    const float* fc2_w  = (const float*)d_in[13];
    const float* fc2_b  = (const float*)d_in[14];
    const float* bnl_g  = (const float*)d_in[15];
    const float* bnl_b  = (const float*)d_in[16];
    const float* watt_w = (const float*)d_in[17];
    const float* watt_b = (const float*)d_in[18];
    const float* wlsm_w = (const float*)d_in[19];
    const float* wlsm_b = (const float*)d_in[20];
    const float* fp_w   = (const float*)d_in[21];
    const float* fp_b   = (const float*)d_in[22];
    const float* bnf_g  = (const float*)d_in[23];
    const float* bnf_b  = (const float*)d_in[24];
    const float* lif_w  = (const float*)d_in[25];
    float* out = (float*)d_out;

    float *bq, *bk, *bv, *ab, *af, *curr, *syn, *mem, *spk, *R, *l, *ga, *gl, *fu, *o, *part, *stats;
    cudaGetSymbolAddress((void**)&bq, g_bq);
    cudaGetSymbolAddress((void**)&bk, g_bk);
    cudaGetSymbolAddress((void**)&bv, g_bv);
    cudaGetSymbolAddress((void**)&ab, g_ab);
    cudaGetSymbolAddress((void**)&af, g_af);
    cudaGetSymbolAddress((void**)&curr, g_curr);
    cudaGetSymbolAddress((void**)&syn, g_syn);
    cudaGetSymbolAddress((void**)&mem, g_mem);
    cudaGetSymbolAddress((void**)&spk, g_spk);
    cudaGetSymbolAddress((void**)&R, g_R);
    cudaGetSymbolAddress((void**)&l, g_l);
    cudaGetSymbolAddress((void**)&ga, g_ga);
    cudaGetSymbolAddress((void**)&gl, g_gl);
    cudaGetSymbolAddress((void**)&fu, g_fu);
    cudaGetSymbolAddress((void**)&o, g_o);
    cudaGetSymbolAddress((void**)&part, g_part);
    cudaGetSymbolAddress((void**)&stats, g_stats);

    const dim3 gC(C_ / BN, TBN_ / BM);     // (3, 196)
    const dim3 gH(HID_ / BN, TBN_ / BM);   // (12, 196) fc1
    const dim3 gR(HID_ / BN, BN_ / BM);    // (12, 49)  rec
    const int nb75k = (NC_ + 255) / 256;
    const int nbBNC = (BNC_ + 255) / 256;
    const int nbMH  = (MH_ + 255) / 256;

    // --- SSA branch ---
    sgemm_nt<<<gC, 256>>>(x, q_w, q_b, bq, TBN_, C_, C_);
    sgemm_nt<<<gC, 256>>>(x, k_w, k_b, bk, TBN_, C_, C_);
    sgemm_nt<<<gC, 256>>>(x, v_w, v_b, bv, TBN_, C_, C_);
    lif_seq<<<nb75k, 256>>>(bq, TB_, NC_, NC_, lif_w, 0);
    lif_seq<<<nb75k, 256>>>(bk, TB_, NC_, NC_, lif_w, 1);
    lif_seq<<<nb75k, 256>>>(bv, TB_, NC_, NC_, lif_w, 2);

    attn_kernel<<<TB_ * H_, 256>>>(bq, bk, bv, ab);
    lif_seq<<<nbBNC, 256>>>(ab, T_, BNC_, BNC_, lif_w, 3);

    sgemm_nt<<<gC, 256>>>(ab, ap_w, ap_b, af, TBN_, C_, C_);
    lif_seq<<<nb75k, 256>>>(af, TB_, NC_, NC_, lif_w, 4);

    // --- LSM branch ---
    sgemm_nt<<<gH, 256>>>(x, fc1_w, fc1_b, curr, TBN_, HID_, C_);
    lsm_step0<<<nbMH, 256>>>(curr, rec_b, syn, mem, spk);
    for (int t = 1; t < T_; t++) {
        sgemm_nt<<<gR, 256>>>(spk + (size_t)(t - 1) * MH_, rec_w, rec_b, R, BN_, HID_, HID_);
        lsm_step<<<nbMH, 256>>>(curr + (size_t)t * MH_, R, syn, mem,
                                spk + (size_t)(t - 1) * MH_, spk + (size_t)t * MH_);
    }
    sgemm_nt<<<gC, 256>>>(spk, fc2_w, fc2_b, l, TBN_, C_, HID_);
    bn_partial<<<98, 384>>>(l, part);
    bn_finalize<<<1, 384>>>(part, stats);
    bn_lif4<<<nbBNC, 256>>>(l, l, stats, bnl_g, bnl_b, lif_w, 5, nullptr);

    // --- ARIG fusion ---
    sgemm_nt<<<gC, 256>>>(af, watt_w, watt_b, ga, TBN_, C_, C_);
    sgemm_nt<<<gC, 256>>>(l,  wlsm_w, wlsm_b, gl, TBN_, C_, C_);
    fuse_kernel<<<nbMH, 256>>>(af, l, ga, gl, fu);
    sgemm_nt<<<gC, 256>>>(fu, fp_w, fp_b, o, TBN_, C_, C_);
    bn_partial<<<98, 384>>>(o, part);
    bn_finalize<<<1, 384>>>(part, stats);
    bn_lif4<<<nbBNC, 256>>>(o, out, stats, bnf_g, bnf_b, lif_w, 6, x);
}